// round 7
// baseline (speedup 1.0000x reference)
#include <cuda_runtime.h>

// Problem constants
#define Bn 8
#define Cn 64
#define Hn 128
#define Wn 128
#define HWn (Hn * Wn)

// Scratch: per-pixel sum of squares of fused over channels (512 KB)
__device__ float g_ss[Bn * HWn];

// ---------------------------------------------------------------------------
// Kernel 1: SS[b,h,w] = sum_c fused[b,c,h,w]^2  (float4: 4 pixels/thread)
// ---------------------------------------------------------------------------
__global__ __launch_bounds__(256) void ss_kernel(const float* __restrict__ fused) {
    int t = blockIdx.x * blockDim.x + threadIdx.x;      // 0 .. B*HW/4-1
    int p = t * 4;
    int b = p >> 14;
    int pos = p & (HWn - 1);
    const float* ptr = fused + (size_t)b * Cn * HWn + pos;
    float4 s = make_float4(0.f, 0.f, 0.f, 0.f);
#pragma unroll 8
    for (int c = 0; c < Cn; c++) {
        float4 v = *reinterpret_cast<const float4*>(ptr + (size_t)c * HWn);
        s.x = fmaf(v.x, v.x, s.x);
        s.y = fmaf(v.y, v.y, s.y);
        s.z = fmaf(v.z, v.z, s.z);
        s.w = fmaf(v.w, v.w, s.w);
    }
    *reinterpret_cast<float4*>(g_ss + p) = s;
}

// ---------------------------------------------------------------------------
// Kernel 2: main refine, 4 px/thread (float4), 4-way channel split.
// One block (4 warps) owns one full (b,h) row of 128 px. Warp q accumulates
// cross-correlations over channels [q*16, q*16+16); partials combine through
// smem; all warps compute the softmax redundantly over their 128 px, then
// each applies weights to its own 16 channels. Halo via overlapping loads.
// ---------------------------------------------------------------------------
__global__ void __launch_bounds__(128)
refine_kernel(const float* __restrict__ fe,
              const float* __restrict__ fused,
              float* __restrict__ out) {
    __shared__ float red[4][32][41];   // [warp][lane][36 ax + 4 sf], stride 41 (odd)

    const int lane = threadIdx.x & 31;
    const int wid  = threadIdx.x >> 5;
    const int row  = blockIdx.x;            // 0 .. 1023
    const int b    = row >> 7;
    const int h    = row & (Hn - 1);
    const int w0   = lane * 4;
    const int c0   = wid * 16;

    const size_t bOff = (size_t)b * Cn * HWn;
    const float* feB  = fe    + bOff + (size_t)c0 * HWn + h * Wn + w0;
    const float* fuB  = fused + bOff + (size_t)c0 * HWn + w0;
    float*       outB = out   + bOff + (size_t)c0 * HWn + h * Wn + w0;

    const bool hasL = (lane > 0);
    const bool hasR = (lane < 31);
    const bool vRow[3] = {h > 0, true, h < Hn - 1};

    // partial cross-correlation accumulators: ax[k][px] = sum_c p_k * f
    float ax[9][4];
#pragma unroll
    for (int k = 0; k < 9; k++)
#pragma unroll
        for (int px = 0; px < 4; px++) ax[k][px] = 0.f;
    float sf[4] = {0.f, 0.f, 0.f, 0.f};

    // ---------------- pass 1: accumulate p*f and f^2 over my 16 channels ----
#pragma unroll 2
    for (int c = 0; c < 16; c++) {
        const float4 F = *reinterpret_cast<const float4*>(feB + (size_t)c * HWn);
        sf[0] = fmaf(F.x, F.x, sf[0]);
        sf[1] = fmaf(F.y, F.y, sf[1]);
        sf[2] = fmaf(F.z, F.z, sf[2]);
        sf[3] = fmaf(F.w, F.w, sf[3]);
#pragma unroll
        for (int dh = 0; dh < 3; dh++) {
            const bool v = vRow[dh];
            const float* rp = fuB + (size_t)c * HWn + (h + dh - 1) * Wn;
            float4 P = make_float4(0.f, 0.f, 0.f, 0.f);
            if (v) P = *reinterpret_cast<const float4*>(rp);
            const float lft = (v && hasL) ? rp[-1] : 0.f;
            const float rgt = (v && hasR) ? rp[4]  : 0.f;
            const int kb = dh * 3;
            // px0: lft P.x P.y | px1: P.x P.y P.z | px2: P.y P.z P.w | px3: P.z P.w rgt
            ax[kb + 0][0] = fmaf(lft, F.x, ax[kb + 0][0]);
            ax[kb + 1][0] = fmaf(P.x, F.x, ax[kb + 1][0]);
            ax[kb + 2][0] = fmaf(P.y, F.x, ax[kb + 2][0]);
            ax[kb + 0][1] = fmaf(P.x, F.y, ax[kb + 0][1]);
            ax[kb + 1][1] = fmaf(P.y, F.y, ax[kb + 1][1]);
            ax[kb + 2][1] = fmaf(P.z, F.y, ax[kb + 2][1]);
            ax[kb + 0][2] = fmaf(P.y, F.z, ax[kb + 0][2]);
            ax[kb + 1][2] = fmaf(P.z, F.z, ax[kb + 1][2]);
            ax[kb + 2][2] = fmaf(P.w, F.z, ax[kb + 2][2]);
            ax[kb + 0][3] = fmaf(P.z, F.w, ax[kb + 0][3]);
            ax[kb + 1][3] = fmaf(P.w, F.w, ax[kb + 1][3]);
            ax[kb + 2][3] = fmaf(rgt, F.w, ax[kb + 2][3]);
        }
    }

    // ---------------- combine partials across the 4 warps ----------------
    {
        float* my = red[wid][lane];
#pragma unroll
        for (int k = 0; k < 9; k++)
#pragma unroll
            for (int px = 0; px < 4; px++) my[k * 4 + px] = ax[k][px];
#pragma unroll
        for (int px = 0; px < 4; px++) my[36 + px] = sf[px];
    }
    __syncthreads();
    {
#pragma unroll
        for (int j = 1; j < 4; j++) {
            const float* ot = red[(wid + j) & 3][lane];
#pragma unroll
            for (int k = 0; k < 9; k++)
#pragma unroll
                for (int px = 0; px < 4; px++) ax[k][px] += ot[k * 4 + px];
#pragma unroll
            for (int px = 0; px < 4; px++) sf[px] += ot[36 + px];
        }
    }

    // ---------------- gather SS at the 9 neighbor positions ----------------
    float ssn[9][4];
    {
        const float* ssB = g_ss + (size_t)b * HWn + w0;
#pragma unroll
        for (int dh = 0; dh < 3; dh++) {
            const bool v = vRow[dh];
            const float* rp = ssB + (h + dh - 1) * Wn;
            float4 S = make_float4(0.f, 0.f, 0.f, 0.f);
            if (v) S = *reinterpret_cast<const float4*>(rp);
            const float lft = (v && hasL) ? rp[-1] : 0.f;
            const float rgt = (v && hasR) ? rp[4]  : 0.f;
            const int kb = dh * 3;
            ssn[kb + 0][0] = lft; ssn[kb + 1][0] = S.x; ssn[kb + 2][0] = S.y;
            ssn[kb + 0][1] = S.x; ssn[kb + 1][1] = S.y; ssn[kb + 2][1] = S.z;
            ssn[kb + 0][2] = S.y; ssn[kb + 1][2] = S.z; ssn[kb + 2][2] = S.w;
            ssn[kb + 0][3] = S.z; ssn[kb + 1][3] = S.w; ssn[kb + 2][3] = rgt;
        }
    }

    // ---------------- softmax weights per pixel (stored back into ax) -------
#pragma unroll
    for (int px = 0; px < 4; px++) {
        float d[9];
#pragma unroll
        for (int k = 0; k < 9; k++) {
            float d2 = ssn[k][px] - 2.f * ax[k][px] + sf[px];
            d[k] = sqrtf(fmaxf(d2, 0.f));
        }
        float mn = d[0];
#pragma unroll
        for (int k = 1; k < 9; k++) mn = fminf(mn, d[k]);
        float s = 0.f;
#pragma unroll
        for (int k = 0; k < 9; k++) {
            float e = __expf(mn - d[k]);
            ax[k][px] = e;
            s += e;
        }
        float inv = 1.f / s;
#pragma unroll
        for (int k = 0; k < 9; k++) ax[k][px] *= inv;
    }

    // ------------- pass 2: weighted neighbor sum + residual (my 16 ch) ------
#pragma unroll 2
    for (int c = 0; c < 16; c++) {
        const float4 F = *reinterpret_cast<const float4*>(feB + (size_t)c * HWn);
        float r0 = F.x, r1 = F.y, r2 = F.z, r3 = F.w;
#pragma unroll
        for (int dh = 0; dh < 3; dh++) {
            const bool v = vRow[dh];
            const float* rp = fuB + (size_t)c * HWn + (h + dh - 1) * Wn;
            float4 P = make_float4(0.f, 0.f, 0.f, 0.f);
            if (v) P = *reinterpret_cast<const float4*>(rp);
            const float lft = (v && hasL) ? rp[-1] : 0.f;
            const float rgt = (v && hasR) ? rp[4]  : 0.f;
            const int kb = dh * 3;
            r0 = fmaf(ax[kb + 0][0], lft, r0);
            r0 = fmaf(ax[kb + 1][0], P.x, r0);
            r0 = fmaf(ax[kb + 2][0], P.y, r0);
            r1 = fmaf(ax[kb + 0][1], P.x, r1);
            r1 = fmaf(ax[kb + 1][1], P.y, r1);
            r1 = fmaf(ax[kb + 2][1], P.z, r1);
            r2 = fmaf(ax[kb + 0][2], P.y, r2);
            r2 = fmaf(ax[kb + 1][2], P.z, r2);
            r2 = fmaf(ax[kb + 2][2], P.w, r2);
            r3 = fmaf(ax[kb + 0][3], P.z, r3);
            r3 = fmaf(ax[kb + 1][3], P.w, r3);
            r3 = fmaf(ax[kb + 2][3], rgt, r3);
        }
        float4 o;
        o.x = r0; o.y = r1; o.z = r2; o.w = r3;
        *reinterpret_cast<float4*>(outB + (size_t)c * HWn) = o;
    }
}

// ---------------------------------------------------------------------------
extern "C" void kernel_launch(void* const* d_in, const int* in_sizes, int n_in,
                              void* d_out, int out_size) {
    const float* fe = (const float*)d_in[0];
    const float* fu = (const float*)d_in[1];
    float* out = (float*)d_out;

    // SS precompute: B*H*W/4 = 32768 threads
    ss_kernel<<<(Bn * HWn / 4) / 256, 256>>>(fu);
    // main: 1024 rows x 4 channel-quarter warps = 4096 warps, 4 warps/block
    refine_kernel<<<1024, 128>>>(fe, fu, out);
}

// round 8
// speedup vs baseline: 1.0007x; 1.0007x over previous
#include <cuda_runtime.h>

// Problem constants
#define Bn 8
#define Cn 64
#define Hn 128
#define Wn 128
#define HWn (Hn * Wn)

// Scratch: per-pixel sum of squares of fused over channels (512 KB)
__device__ float g_ss[Bn * HWn];

// ---------------------------------------------------------------------------
// Kernel 1: SS[b,h,w] = sum_c fused[b,c,h,w]^2  (float4: 4 pixels/thread)
// ---------------------------------------------------------------------------
__global__ __launch_bounds__(256) void ss_kernel(const float* __restrict__ fused) {
    int t = blockIdx.x * blockDim.x + threadIdx.x;      // 0 .. B*HW/4-1
    int p = t * 4;
    int b = p >> 14;
    int pos = p & (HWn - 1);
    const float* ptr = fused + (size_t)b * Cn * HWn + pos;
    float4 s = make_float4(0.f, 0.f, 0.f, 0.f);
#pragma unroll 8
    for (int c = 0; c < Cn; c++) {
        float4 v = *reinterpret_cast<const float4*>(ptr + (size_t)c * HWn);
        s.x = fmaf(v.x, v.x, s.x);
        s.y = fmaf(v.y, v.y, s.y);
        s.z = fmaf(v.z, v.z, s.z);
        s.w = fmaf(v.w, v.w, s.w);
    }
    *reinterpret_cast<float4*>(g_ss + p) = s;
}

// ---------------------------------------------------------------------------
// Kernel 2: main refine, 4 px/thread (float4), 4-way channel split.
// One block (4 warps) owns one full (b,h) row of 128 px. Warp q accumulates
// cross-correlations over channels [q*16, q*16+16); partials combine through
// smem; all warps compute the softmax redundantly over their 128 px, then
// each applies weights to its own 16 channels. Halo via overlapping loads.
// ---------------------------------------------------------------------------
__global__ void __launch_bounds__(128)
refine_kernel(const float* __restrict__ fe,
              const float* __restrict__ fused,
              float* __restrict__ out) {
    __shared__ float red[4][32][41];   // [warp][lane][36 ax + 4 sf], stride 41 (odd)

    const int lane = threadIdx.x & 31;
    const int wid  = threadIdx.x >> 5;
    const int row  = blockIdx.x;            // 0 .. 1023
    const int b    = row >> 7;
    const int h    = row & (Hn - 1);
    const int w0   = lane * 4;
    const int c0   = wid * 16;

    const size_t bOff = (size_t)b * Cn * HWn;
    const float* feB  = fe    + bOff + (size_t)c0 * HWn + h * Wn + w0;
    const float* fuB  = fused + bOff + (size_t)c0 * HWn + w0;
    float*       outB = out   + bOff + (size_t)c0 * HWn + h * Wn + w0;

    const bool hasL = (lane > 0);
    const bool hasR = (lane < 31);
    const bool vRow[3] = {h > 0, true, h < Hn - 1};

    // partial cross-correlation accumulators: ax[k][px] = sum_c p_k * f
    float ax[9][4];
#pragma unroll
    for (int k = 0; k < 9; k++)
#pragma unroll
        for (int px = 0; px < 4; px++) ax[k][px] = 0.f;
    float sf[4] = {0.f, 0.f, 0.f, 0.f};

    // ---------------- pass 1: accumulate p*f and f^2 over my 16 channels ----
#pragma unroll 2
    for (int c = 0; c < 16; c++) {
        const float4 F = *reinterpret_cast<const float4*>(feB + (size_t)c * HWn);
        sf[0] = fmaf(F.x, F.x, sf[0]);
        sf[1] = fmaf(F.y, F.y, sf[1]);
        sf[2] = fmaf(F.z, F.z, sf[2]);
        sf[3] = fmaf(F.w, F.w, sf[3]);
#pragma unroll
        for (int dh = 0; dh < 3; dh++) {
            const bool v = vRow[dh];
            const float* rp = fuB + (size_t)c * HWn + (h + dh - 1) * Wn;
            float4 P = make_float4(0.f, 0.f, 0.f, 0.f);
            if (v) P = *reinterpret_cast<const float4*>(rp);
            const float lft = (v && hasL) ? rp[-1] : 0.f;
            const float rgt = (v && hasR) ? rp[4]  : 0.f;
            const int kb = dh * 3;
            // px0: lft P.x P.y | px1: P.x P.y P.z | px2: P.y P.z P.w | px3: P.z P.w rgt
            ax[kb + 0][0] = fmaf(lft, F.x, ax[kb + 0][0]);
            ax[kb + 1][0] = fmaf(P.x, F.x, ax[kb + 1][0]);
            ax[kb + 2][0] = fmaf(P.y, F.x, ax[kb + 2][0]);
            ax[kb + 0][1] = fmaf(P.x, F.y, ax[kb + 0][1]);
            ax[kb + 1][1] = fmaf(P.y, F.y, ax[kb + 1][1]);
            ax[kb + 2][1] = fmaf(P.z, F.y, ax[kb + 2][1]);
            ax[kb + 0][2] = fmaf(P.y, F.z, ax[kb + 0][2]);
            ax[kb + 1][2] = fmaf(P.z, F.z, ax[kb + 1][2]);
            ax[kb + 2][2] = fmaf(P.w, F.z, ax[kb + 2][2]);
            ax[kb + 0][3] = fmaf(P.z, F.w, ax[kb + 0][3]);
            ax[kb + 1][3] = fmaf(P.w, F.w, ax[kb + 1][3]);
            ax[kb + 2][3] = fmaf(rgt, F.w, ax[kb + 2][3]);
        }
    }

    // ---------------- combine partials across the 4 warps ----------------
    {
        float* my = red[wid][lane];
#pragma unroll
        for (int k = 0; k < 9; k++)
#pragma unroll
            for (int px = 0; px < 4; px++) my[k * 4 + px] = ax[k][px];
#pragma unroll
        for (int px = 0; px < 4; px++) my[36 + px] = sf[px];
    }
    __syncthreads();
    {
#pragma unroll
        for (int j = 1; j < 4; j++) {
            const float* ot = red[(wid + j) & 3][lane];
#pragma unroll
            for (int k = 0; k < 9; k++)
#pragma unroll
                for (int px = 0; px < 4; px++) ax[k][px] += ot[k * 4 + px];
#pragma unroll
            for (int px = 0; px < 4; px++) sf[px] += ot[36 + px];
        }
    }

    // ---------------- gather SS at the 9 neighbor positions ----------------
    float ssn[9][4];
    {
        const float* ssB = g_ss + (size_t)b * HWn + w0;
#pragma unroll
        for (int dh = 0; dh < 3; dh++) {
            const bool v = vRow[dh];
            const float* rp = ssB + (h + dh - 1) * Wn;
            float4 S = make_float4(0.f, 0.f, 0.f, 0.f);
            if (v) S = *reinterpret_cast<const float4*>(rp);
            const float lft = (v && hasL) ? rp[-1] : 0.f;
            const float rgt = (v && hasR) ? rp[4]  : 0.f;
            const int kb = dh * 3;
            ssn[kb + 0][0] = lft; ssn[kb + 1][0] = S.x; ssn[kb + 2][0] = S.y;
            ssn[kb + 0][1] = S.x; ssn[kb + 1][1] = S.y; ssn[kb + 2][1] = S.z;
            ssn[kb + 0][2] = S.y; ssn[kb + 1][2] = S.z; ssn[kb + 2][2] = S.w;
            ssn[kb + 0][3] = S.z; ssn[kb + 1][3] = S.w; ssn[kb + 2][3] = rgt;
        }
    }

    // ---------------- softmax weights per pixel (stored back into ax) -------
#pragma unroll
    for (int px = 0; px < 4; px++) {
        float d[9];
#pragma unroll
        for (int k = 0; k < 9; k++) {
            float d2 = ssn[k][px] - 2.f * ax[k][px] + sf[px];
            d[k] = sqrtf(fmaxf(d2, 0.f));
        }
        float mn = d[0];
#pragma unroll
        for (int k = 1; k < 9; k++) mn = fminf(mn, d[k]);
        float s = 0.f;
#pragma unroll
        for (int k = 0; k < 9; k++) {
            float e = __expf(mn - d[k]);
            ax[k][px] = e;
            s += e;
        }
        float inv = 1.f / s;
#pragma unroll
        for (int k = 0; k < 9; k++) ax[k][px] *= inv;
    }

    // ------------- pass 2: weighted neighbor sum + residual (my 16 ch) ------
#pragma unroll 2
    for (int c = 0; c < 16; c++) {
        const float4 F = *reinterpret_cast<const float4*>(feB + (size_t)c * HWn);
        float r0 = F.x, r1 = F.y, r2 = F.z, r3 = F.w;
#pragma unroll
        for (int dh = 0; dh < 3; dh++) {
            const bool v = vRow[dh];
            const float* rp = fuB + (size_t)c * HWn + (h + dh - 1) * Wn;
            float4 P = make_float4(0.f, 0.f, 0.f, 0.f);
            if (v) P = *reinterpret_cast<const float4*>(rp);
            const float lft = (v && hasL) ? rp[-1] : 0.f;
            const float rgt = (v && hasR) ? rp[4]  : 0.f;
            const int kb = dh * 3;
            r0 = fmaf(ax[kb + 0][0], lft, r0);
            r0 = fmaf(ax[kb + 1][0], P.x, r0);
            r0 = fmaf(ax[kb + 2][0], P.y, r0);
            r1 = fmaf(ax[kb + 0][1], P.x, r1);
            r1 = fmaf(ax[kb + 1][1], P.y, r1);
            r1 = fmaf(ax[kb + 2][1], P.z, r1);
            r2 = fmaf(ax[kb + 0][2], P.y, r2);
            r2 = fmaf(ax[kb + 1][2], P.z, r2);
            r2 = fmaf(ax[kb + 2][2], P.w, r2);
            r3 = fmaf(ax[kb + 0][3], P.z, r3);
            r3 = fmaf(ax[kb + 1][3], P.w, r3);
            r3 = fmaf(ax[kb + 2][3], rgt, r3);
        }
        float4 o;
        o.x = r0; o.y = r1; o.z = r2; o.w = r3;
        *reinterpret_cast<float4*>(outB + (size_t)c * HWn) = o;
    }
}

// ---------------------------------------------------------------------------
extern "C" void kernel_launch(void* const* d_in, const int* in_sizes, int n_in,
                              void* d_out, int out_size) {
    const float* fe = (const float*)d_in[0];
    const float* fu = (const float*)d_in[1];
    float* out = (float*)d_out;

    // SS precompute: B*H*W/4 = 32768 threads
    ss_kernel<<<(Bn * HWn / 4) / 256, 256>>>(fu);
    // main: 1024 rows x 4 channel-quarter warps = 4096 warps, 4 warps/block
    refine_kernel<<<1024, 128>>>(fe, fu, out);
}